// round 6
// baseline (speedup 1.0000x reference)
#include <cuda_runtime.h>
#include <math.h>

// Problem constants (fixed by the dataset): B=32, S=1024, T=64, ENC=768, HID=256
#define BB  32
#define TT  64
#define ENC 768
#define HID 256

// Scratch (no allocations allowed)
__device__ float g_e[BB * TT];   // e[b,k] = enc[b, ids[b,k], :] . w_e   (k in [1,len)), else 0

// ---------------------------------------------------------------------------
// Algebra: scores[b,j,k] = a[b,j] + e[b,k] + fc_b is rank-1 separable, so
//   loss_j = lse[b,j] - s_next[b,j]
//          = (a[j]+fb+logsumexp_{j<k<len} e[k]) - (a[j]+e[j+1]+fb)
//          = logsumexp_{k=j+1..len-1}(e[b,k]) - e[b,j+1]
// The entire LSTM path (a[j]) and fc_b cancel exactly. Masked entries hit
// exp(-1e30 - m) == 0 in fp32, so dropping them is bit-compatible.
// ---------------------------------------------------------------------------

// K1: one warp per (b,k): gathered 768-dot with w_e = fc_w[HID : HID+ENC]
__global__ void __launch_bounds__(256) e_kernel(const float* __restrict__ enc,
                                                const float* __restrict__ fc_w,
                                                const int*   __restrict__ ids,
                                                const int*   __restrict__ lens,
                                                int S) {
    int w    = (blockIdx.x * blockDim.x + threadIdx.x) >> 5;  // global warp id
    int lane = threadIdx.x & 31;
    if (w >= BB * TT) return;
    int b = w >> 6;         // / TT
    int k = w & (TT - 1);   // % TT

    float e = 0.0f;
    int len = __ldg(&lens[b]);
    if (k >= 1 && k < len) {            // k=0 never appears in any suffix LSE
        int row = __ldg(&ids[b * TT + k]);
        const float4* x  = (const float4*)(enc + ((long long)b * S + row) * ENC);
        const float4* wv = (const float4*)(fc_w + HID);   // +256 floats = 1KB, 16B-aligned
        float acc = 0.0f;
        #pragma unroll
        for (int i = 0; i < 6; ++i) {   // 32 lanes * 6 float4 * 4 = 768
            float4 xv = __ldg(&x[lane + 32 * i]);
            float4 ww = __ldg(&wv[lane + 32 * i]);
            acc += xv.x * ww.x + xv.y * ww.y + xv.z * ww.z + xv.w * ww.w;
        }
        #pragma unroll
        for (int o = 16; o; o >>= 1)
            acc += __shfl_down_sync(0xffffffffu, acc, o);
        e = acc;  // only lane 0's value matters
    }
    if (lane == 0) g_e[w] = e;
}

// K2 (fused scan + final reduce): ONE block, 256 threads.
//  - stage all of g_e (8KB) into shared, coalesced
//  - lane b of warp 0 runs batch b's serial suffix-logsumexp scan from shared
//  - warp-reduce loss & count, write scalar result
__global__ void __launch_bounds__(256) scan_final_kernel(const int* __restrict__ lens,
                                                         float* __restrict__ out) {
    __shared__ float se[BB * TT];
    for (int i = threadIdx.x; i < BB * TT; i += 256)
        se[i] = g_e[i];
    __syncthreads();

    if (threadIdx.x < 32) {
        int b = threadIdx.x;
        int len = __ldg(&lens[b]);      // len in [2, 64]
        const float* eb = &se[b * TT];
        float m = -INFINITY;
        float s = 0.0f;
        float loss = 0.0f;
        for (int k = len - 1; k >= 1; --k) {
            float v = eb[k];
            if (v > m) {                // first iter: expf(-inf)=0 -> s=1, m=v
                s = s * expf(m - v) + 1.0f;
                m = v;
            } else {
                s += expf(v - m);
            }
            loss += m + logf(s) - v;    // = lse[b,k-1] - s_next[b,k-1]
        }
        float cnt = (float)(len - 1);
        #pragma unroll
        for (int o = 16; o; o >>= 1) {
            loss += __shfl_down_sync(0xffffffffu, loss, o);
            cnt  += __shfl_down_sync(0xffffffffu, cnt,  o);
        }
        if (b == 0) out[0] = loss / cnt;
    }
}

// ---------------------------------------------------------------------------
// Inputs (metadata order): 0 encoder_output f32 [B,S,ENC], 1 W_ih, 2 W_hh,
// 3 b_ih, 4 b_hh, 5 fc_w f32 [1, ENC+HID], 6 fc_b, 7 his_turn_end_ids i32
// [B,T], 8 turn_lengths i32 [B].  Output: 1 float.
// W_ih/W_hh/biases/fc_b cancel out of the loss and are never read.
// ---------------------------------------------------------------------------
extern "C" void kernel_launch(void* const* d_in, const int* in_sizes, int n_in,
                              void* d_out, int out_size) {
    const float* enc  = (const float*)d_in[0];
    const float* fc_w = (const float*)d_in[5];
    const int*   ids  = (const int*)d_in[7];
    const int*   lens = (const int*)d_in[8];
    int S = in_sizes[0] / (BB * ENC);   // row stride of encoder_output

    e_kernel<<<256, 256>>>(enc, fc_w, ids, lens, S);          // 2048 warps
    scan_final_kernel<<<1, 256>>>(lens, (float*)d_out);
}

// round 9
// speedup vs baseline: 1.5970x; 1.5970x over previous
#include <cuda_runtime.h>
#include <math.h>

// Problem constants (fixed by the dataset): B=32, S=1024, T=64, ENC=768, HID=256
#define BB  32
#define TT  64
#define ENC 768
#define HID 256
#define NBLOCKS 256   // 256 blocks x 8 warps = 2048 warps = BB*TT

// Scratch (no allocations allowed)
__device__ float    g_e[BB * TT];  // e[b,k] = enc[b, ids[b,k], :] . w_e (k in [1,len)), else 0
__device__ unsigned g_arrive;      // zero-init at load; last block resets to 0 each call

// ---------------------------------------------------------------------------
// Algebra: scores[b,j,k] = a[b,j] + e[b,k] + fc_b is rank-1 separable, so
//   loss_j = lse[b,j] - s_next[b,j]
//          = logsumexp_{k=j+1..len-1}(e[b,k]) - e[b,j+1]
// The entire LSTM path (a[j]) and fc_b cancel exactly. Masked entries hit
// exp(-1e30 - m) == 0 in fp32, so dropping them is bit-compatible.
//
// Single fused kernel:
//   Phase 1: one warp per (b,k) computes the gathered 768-dot e[b,k].
//   Phase 2: last-arriving block (threadfence-reduction pattern) stages g_e
//            and runs 32 concurrent per-batch suffix-LSE scans on warp 0,
//            branchless, with MUFU __expf/__logf on the serial chain.
// ---------------------------------------------------------------------------
__global__ void __launch_bounds__(256) fused_kernel(const float* __restrict__ enc,
                                                    const float* __restrict__ fc_w,
                                                    const int*   __restrict__ ids,
                                                    const int*   __restrict__ lens,
                                                    int S, float* __restrict__ out) {
    __shared__ float se[BB * TT];   // 8KB, used only by the last block
    __shared__ unsigned is_last;

    // ---- Phase 1: per-warp gathered dot --------------------------------
    int w    = (blockIdx.x * blockDim.x + threadIdx.x) >> 5;  // global warp id
    int lane = threadIdx.x & 31;
    int b = w >> 6;         // / TT
    int k = w & (TT - 1);   // % TT

    float e = 0.0f;
    int len = __ldg(&lens[b]);
    if (k >= 1 && k < len) {            // k=0 never appears in any suffix LSE
        int row = __ldg(&ids[b * TT + k]);
        const float4* x  = (const float4*)(enc + ((long long)b * S + row) * ENC);
        const float4* wv = (const float4*)(fc_w + HID);   // +256 floats, 16B-aligned
        float acc = 0.0f;
        #pragma unroll
        for (int i = 0; i < 6; ++i) {   // 32 lanes * 6 float4 * 4 = 768
            float4 xv = __ldg(&x[lane + 32 * i]);
            float4 ww = __ldg(&wv[lane + 32 * i]);
            acc += xv.x * ww.x + xv.y * ww.y + xv.z * ww.z + xv.w * ww.w;
        }
        #pragma unroll
        for (int o = 16; o; o >>= 1)
            acc += __shfl_down_sync(0xffffffffu, acc, o);
        e = acc;
    }
    if (lane == 0) g_e[w] = e;

    // ---- Arrival: publish writes, count blocks -------------------------
    __threadfence();                    // make g_e writes visible device-wide
    __syncthreads();                    // all warps of this block done
    if (threadIdx.x == 0) {
        unsigned t = atomicAdd(&g_arrive, 1u);
        is_last = (t == NBLOCKS - 1) ? 1u : 0u;
    }
    __syncthreads();
    if (!is_last) return;

    // ---- Phase 2: last block only --------------------------------------
    if (threadIdx.x == 0) g_arrive = 0;     // reset for next graph replay
    __threadfence();

    for (int i = threadIdx.x; i < BB * TT; i += 256)
        se[i] = g_e[i];                     // L2-hot, coalesced
    __syncthreads();

    if (threadIdx.x < 32) {
        int bb = threadIdx.x;
        int L  = __ldg(&lens[bb]);          // L in [2, 64]
        const float* eb = &se[bb * TT];

        // Suffix-LSE scan, invariant: before processing k, (m,s) is the
        // LSE state over {e[k+1 .. L-1]}. Term for j=k: (m + log s) - e[k+1].
        float m = eb[L - 1];
        float s = 1.0f;
        float loss = 0.0f;                  // j = L-2 term is exactly 0
        for (int k = L - 2; k >= 1; --k) {
            loss += (m + __logf(s)) - eb[k + 1];
            float v  = eb[k];
            float nm = fmaxf(m, v);
            s = s * __expf(m - nm) + __expf(v - nm);
            m = nm;
        }
        loss += (m + __logf(s)) - eb[1];    // j = 0 term

        float cnt = (float)(L - 1);
        #pragma unroll
        for (int o = 16; o; o >>= 1) {
            loss += __shfl_down_sync(0xffffffffu, loss, o);
            cnt  += __shfl_down_sync(0xffffffffu, cnt,  o);
        }
        if (bb == 0) out[0] = loss / cnt;
    }
}

// ---------------------------------------------------------------------------
// Inputs (metadata order): 0 encoder_output f32 [B,S,ENC], 1 W_ih, 2 W_hh,
// 3 b_ih, 4 b_hh, 5 fc_w f32 [1, ENC+HID], 6 fc_b, 7 his_turn_end_ids i32
// [B,T], 8 turn_lengths i32 [B].  Output: 1 float.
// W_ih/W_hh/biases/fc_b cancel out of the loss and are never read.
// ---------------------------------------------------------------------------
extern "C" void kernel_launch(void* const* d_in, const int* in_sizes, int n_in,
                              void* d_out, int out_size) {
    const float* enc  = (const float*)d_in[0];
    const float* fc_w = (const float*)d_in[5];
    const int*   ids  = (const int*)d_in[7];
    const int*   lens = (const int*)d_in[8];
    int S = in_sizes[0] / (BB * ENC);   // row stride of encoder_output

    fused_kernel<<<NBLOCKS, 256>>>(enc, fc_w, ids, lens, S, (float*)d_out);
}